// round 10
// baseline (speedup 1.0000x reference)
#include <cuda_runtime.h>
#include <cuda_fp16.h>
#include <cstdint>
#include <math_constants.h>

#define BB 8192
#define DD 256
#define TI 128
#define TJ 128
#define KC 64              // fp16 k-chunk = 128B rows
#define NCH (DD / KC)      // 4
#define NB  (BB / TI)      // 64
#define NTILES (NB * (NB + 1) / 2)   // 2080
#define GRID 296           // persistent: 148 SMs x 2 CTAs
#define FULLK 7            // strided tiles per CTA (7*296 = 2072)
#define EXTRA (NTILES - FULLK * GRID)  // 8
#define MARGIN_F 0.3f

// dynamic smem layout: 3-stage
#define OFF_SQJ    0
#define OFF_LBLJ   512
#define OFF_SQI    1024
#define OFF_LBLI   1536
#define OFF_STAGE  2048
#define STAGE_BYTES 32768          // A tile 16KB + B tile 16KB
#define OFF_B      16384
#define SMEM_DYN   (OFF_STAGE + 3 * STAGE_BYTES)

__device__ __half g_xh[BB * DD];
__device__ float g_sq[BB];
__device__ unsigned int g_maxenc[BB];
__device__ unsigned int g_minenc[BB];
__device__ unsigned int g_done = 0;

__device__ __forceinline__ uint32_t smem_u32(const void* p) {
    uint32_t a;
    asm("{ .reg .u64 t; cvta.to.shared.u64 t, %1; cvt.u32.u64 %0, t; }" : "=r"(a) : "l"(p));
    return a;
}
__device__ __forceinline__ unsigned enc_f(float f) {
    unsigned u = __float_as_uint(f);
    return (u & 0x80000000u) ? ~u : (u | 0x80000000u);
}
__device__ __forceinline__ float dec_f(unsigned u) {
    return (u & 0x80000000u) ? __uint_as_float(u & 0x7FFFFFFFu) : __uint_as_float(~u);
}
#define CP_ASYNC(dst, src) \
    asm volatile("cp.async.cg.shared.global [%0], [%1], 16;" :: "r"(dst), "l"(src) : "memory")
#define CP_COMMIT() asm volatile("cp.async.commit_group;" ::: "memory")
#define CP_WAIT(n)  asm volatile("cp.async.wait_group " #n ";" ::: "memory")
#define LDSM4(r0,r1,r2,r3,a) \
    asm volatile("ldmatrix.sync.aligned.m8n8.x4.shared.b16 {%0,%1,%2,%3}, [%4];" \
                 : "=r"(r0),"=r"(r1),"=r"(r2),"=r"(r3) : "r"(a))
#define MMAH(d,a,b0,b1) \
    asm volatile("mma.sync.aligned.m16n8k16.row.col.f32.f16.f16.f32 " \
                 "{%0,%1,%2,%3}, {%4,%5,%6,%7}, {%8,%9}, {%0,%1,%2,%3};" \
                 : "+f"(d[0]),"+f"(d[1]),"+f"(d[2]),"+f"(d[3]) \
                 : "r"(a[0]),"r"(a[1]),"r"(a[2]),"r"(a[3]),"r"(b0),"r"(b1))

// ---------- 0) fp32 -> fp16, fused row norms + mining init (4 float4/thread) ----------
__global__ void prep_kernel(const float* __restrict__ x) {
    __shared__ float part[32];
    int tid = threadIdx.x, lane = tid & 31, wid = tid >> 5;
    float s[4];
    #pragma unroll
    for (int h = 0; h < 4; h++) {
        int i = blockIdx.x * 1024 + h * 256 + tid;     // float4 index; 16 rows/block
        float4 v = ((const float4*)x)[i];
        ((__half2*)g_xh)[2*i]   = __floats2half2_rn(v.x, v.y);
        ((__half2*)g_xh)[2*i+1] = __floats2half2_rn(v.z, v.w);
        s[h] = fmaf(v.x, v.x, fmaf(v.y, v.y, fmaf(v.z, v.z, v.w * v.w)));
    }
    #pragma unroll
    for (int h = 0; h < 4; h++) {
        float t = s[h];
        #pragma unroll
        for (int o = 16; o; o >>= 1) t += __shfl_down_sync(0xffffffffu, t, o);
        if (lane == 0) part[h * 8 + wid] = t;          // each warp covers half a row
    }
    __syncthreads();
    if (tid < 16) {
        int row = blockIdx.x * 16 + tid;
        g_sq[row] = part[tid * 2] + part[tid * 2 + 1];
        g_maxenc[row] = 0u;
        g_minenc[row] = 0xFFFFFFFFu;
    }
}

// decode upper-triangle tile index -> (bi, bj)
__device__ __forceinline__ void tile2ij(int tile, int& bi, int& bj) {
    int rem = tile; bi = 0;
    while (rem >= NB - bi) { rem -= NB - bi; bi++; }
    bj = bi + rem;
}

// ---------- 1) fp16 Gram tiles, 3-stage pipeline, fused final reduce ----------
__global__ void __launch_bounds__(256, 2)
triplet_mma(const int* __restrict__ tgt, float* __restrict__ out) {
    extern __shared__ char smem[];
    __shared__ int s_win;
    const uint32_t sb = smem_u32(smem);
    const int tid = threadIdx.x, lane = tid & 31, wid = tid >> 5;
    const int wm = wid >> 2, wn = wid & 3;          // warp tile: rows wm*64, cols wn*32
    const int bx = blockIdx.x;

    auto tileof = [&](int w) {
        return (w < FULLK) ? (bx + w * GRID) : (FULLK * GRID + bx);
    };
    auto issue_loads = [&](int i0, int j0, int c, int st) {
        const uint32_t abase = sb + OFF_STAGE + st * STAGE_BYTES;
        const uint32_t bbase = abase + OFF_B;
        const int kb = c * KC;
        #pragma unroll
        for (int t = 0; t < 4; t++) {
            int idx = t * 256 + tid;           // 0..1023
            int row = idx >> 3;                // 0..127
            int ch  = idx & 7;
            uint32_t d = (uint32_t)((ch ^ (row & 7)) * 16);
            const __half* sA = g_xh + (size_t)(i0 + row) * DD + kb + ch * 8;
            const __half* sB = g_xh + (size_t)(j0 + row) * DD + kb + ch * 8;
            CP_ASYNC(abase + row * 128 + d, sA);
            CP_ASYNC(bbase + row * 128 + d, sB);
        }
        CP_COMMIT();
    };

    const int n = FULLK + (bx < EXTRA ? 1 : 0);
    const int total = n * 4;
    int bi, bj, nbi = 0, nbj = 0;
    tile2ij(tileof(0), bi, bj);
    issue_loads(bi * TI, bj * TJ, 0, 0);   // p=0 -> stage 0
    issue_loads(bi * TI, bj * TJ, 1, 1);   // p=1 -> stage 1

    for (int w = 0; w < n; w++) {
        const int i0 = bi * TI, j0 = bj * TJ;
        const bool diag = (bi == bj);
        const bool hn = (w + 1 < n);
        if (hn) tile2ij(tileof(w + 1), nbi, nbj);

        float acc[4][4][4];
        #pragma unroll
        for (int mt = 0; mt < 4; mt++)
            #pragma unroll
            for (int nt = 0; nt < 4; nt++)
                #pragma unroll
                for (int e = 0; e < 4; e++) acc[mt][nt][e] = 0.f;

        for (int c = 0; c < NCH; c++) {
            const int p = w * 4 + c;
            if (p == total - 1) { CP_WAIT(0); } else { CP_WAIT(1); }
            __syncthreads();          // chunk p landed for all; prev compute done
            if (c == 0) {             // safe: after sync (prev epilogue finished)
                if (tid < TJ) {
                    ((float*)(smem + OFF_SQJ))[tid] = g_sq[j0 + tid];
                    ((int*)(smem + OFF_LBLJ))[tid]  = tgt[j0 + tid];
                } else {
                    int r = tid - TJ;
                    ((float*)(smem + OFF_SQI))[r] = g_sq[i0 + r];
                    ((int*)(smem + OFF_LBLI))[r]  = tgt[i0 + r];
                }
            }
            const int q = p + 2;
            if (q < total) {          // issue-after-sync: stage (q%3) is free
                int qw = q >> 2, qc = q & 3;
                int qi0 = (qw == w) ? i0 : nbi * TI;
                int qj0 = (qw == w) ? j0 : nbj * TJ;
                issue_loads(qi0, qj0, qc, q % 3);
            }

            const uint32_t abase = sb + OFF_STAGE + (p % 3) * STAGE_BYTES;
            const uint32_t bbase = abase + OFF_B;
            #pragma unroll
            for (int ks = 0; ks < 4; ks++) {
                uint32_t bh[8];
                #pragma unroll
                for (int pp = 0; pp < 2; pp++) {
                    int nrow = wn * 32 + pp * 16 + (lane & 7) + ((lane >> 4) << 3);
                    int ch   = ks * 2 + ((lane >> 3) & 1);
                    uint32_t a_ = bbase + nrow * 128 + (uint32_t)((ch ^ (nrow & 7)) * 16);
                    LDSM4(bh[pp*4+0], bh[pp*4+1], bh[pp*4+2], bh[pp*4+3], a_);
                }
                #pragma unroll
                for (int mt = 0; mt < 4; mt++) {
                    int arow = wm * 64 + mt * 16 + (lane & 15);
                    int ch   = ks * 2 + (lane >> 4);
                    uint32_t a_ = abase + arow * 128 + (uint32_t)((ch ^ (arow & 7)) * 16);
                    uint32_t ar[4];
                    LDSM4(ar[0], ar[1], ar[2], ar[3], a_);
                    #pragma unroll
                    for (int nt = 0; nt < 4; nt++) {
                        uint32_t b0 = bh[(nt >> 1) * 4 + (nt & 1) * 2];
                        uint32_t b1 = bh[(nt >> 1) * 4 + (nt & 1) * 2 + 1];
                        MMAH(acc[mt][nt], ar, b0, b1);
                    }
                }
            }
        }

        const float* sSqJ  = (const float*)(smem + OFF_SQJ);
        const int*   sLblJ = (const int*)(smem + OFF_LBLJ);
        const float* sSqI  = (const float*)(smem + OFF_SQI);
        const int*   sLblI = (const int*)(smem + OFF_LBLI);

        // ---- row-side mining: val = sq[j] - 2*dot (sq[i] cancels downstream) ----
        #pragma unroll
        for (int mt = 0; mt < 4; mt++) {
            #pragma unroll
            for (int half = 0; half < 2; half++) {
                int li    = wm * 64 + mt * 16 + (lane >> 2) + half * 8;
                int mylbl = sLblI[li];
                float mp = -CUDART_INF_F, mn = CUDART_INF_F;
                #pragma unroll
                for (int nt = 0; nt < 4; nt++) {
                    int jl = wn * 32 + nt * 8 + (lane & 3) * 2;
                    float v0 = fmaf(-2.f, acc[mt][nt][half * 2],     sSqJ[jl]);
                    float v1 = fmaf(-2.f, acc[mt][nt][half * 2 + 1], sSqJ[jl + 1]);
                    if (sLblJ[jl]     == mylbl) mp = fmaxf(mp, v0); else mn = fminf(mn, v0);
                    if (sLblJ[jl + 1] == mylbl) mp = fmaxf(mp, v1); else mn = fminf(mn, v1);
                }
                #pragma unroll
                for (int o = 1; o <= 2; o <<= 1) {
                    mp = fmaxf(mp, __shfl_xor_sync(0xffffffffu, mp, o));
                    mn = fminf(mn, __shfl_xor_sync(0xffffffffu, mn, o));
                }
                if ((lane & 3) == 0) {
                    atomicMax(&g_maxenc[i0 + li], enc_f(mp));
                    atomicMin(&g_minenc[i0 + li], enc_f(mn));
                }
            }
        }
        // ---- col-side mining (off-diag only): val = sq[i] - 2*dot ----
        if (!diag) {
            #pragma unroll
            for (int nt = 0; nt < 4; nt++) {
                #pragma unroll
                for (int e = 0; e < 2; e++) {
                    int lj    = wn * 32 + nt * 8 + (lane & 3) * 2 + e;
                    int jlbl  = sLblJ[lj];
                    float mp = -CUDART_INF_F, mn = CUDART_INF_F;
                    #pragma unroll
                    for (int mt = 0; mt < 4; mt++) {
                        #pragma unroll
                        for (int half = 0; half < 2; half++) {
                            int li = wm * 64 + mt * 16 + (lane >> 2) + half * 8;
                            float v = fmaf(-2.f, acc[mt][nt][half * 2 + e], sSqI[li]);
                            if (sLblI[li] == jlbl) mp = fmaxf(mp, v);
                            else                   mn = fminf(mn, v);
                        }
                    }
                    #pragma unroll
                    for (int o = 4; o <= 16; o <<= 1) {
                        mp = fmaxf(mp, __shfl_xor_sync(0xffffffffu, mp, o));
                        mn = fminf(mn, __shfl_xor_sync(0xffffffffu, mn, o));
                    }
                    if (lane < 4) {
                        atomicMax(&g_maxenc[j0 + lj], enc_f(mp));
                        atomicMin(&g_minenc[j0 + lj], enc_f(mn));
                    }
                }
            }
        }

        bi = nbi; bj = nbj;
    }

    // ---- fused final reduce: last CTA to finish computes loss & precision ----
    __syncthreads();
    if (tid == 0) {
        __threadfence();
        unsigned old = atomicAdd(&g_done, 1u);
        s_win = (old == GRID - 1) ? 1 : 0;
    }
    __syncthreads();
    if (s_win) {
        __threadfence();
        __shared__ float wl[8], wp[8];
        float lsum = 0.f, pcnt = 0.f;
        for (int i = tid; i < BB; i += 256) {
            float mp = dec_f(__ldcg(&g_maxenc[i]));
            float mn = dec_f(__ldcg(&g_minenc[i]));
            float d = mp - mn + MARGIN_F;        // == dist_ap - dist_an + margin
            lsum += (d > 0.f) ? d : 0.f;
            pcnt += (mn > mp) ? 1.f : 0.f;
        }
        #pragma unroll
        for (int o = 16; o; o >>= 1) {
            lsum += __shfl_down_sync(0xffffffffu, lsum, o);
            pcnt += __shfl_down_sync(0xffffffffu, pcnt, o);
        }
        if (lane == 0) { wl[wid] = lsum; wp[wid] = pcnt; }
        __syncthreads();
        if (wid == 0 && lane < 8) {
            float l = wl[lane], p = wp[lane];
            #pragma unroll
            for (int o = 4; o; o >>= 1) {
                l += __shfl_down_sync(0x000000ffu, l, o);
                p += __shfl_down_sync(0x000000ffu, p, o);
            }
            if (lane == 0) {
                out[0] = l / (float)BB;
                out[1] = p / (float)BB;
                g_done = 0;                      // reset for next graph replay
            }
        }
    }
}

extern "C" void kernel_launch(void* const* d_in, const int* in_sizes, int n_in,
                              void* d_out, int out_size) {
    const float* x = (const float*)d_in[0];
    const int*   t = (const int*)d_in[1];   // JAX x64-disabled: int32
    float*       o = (float*)d_out;

    cudaFuncSetAttribute(triplet_mma, cudaFuncAttributeMaxDynamicSharedMemorySize, SMEM_DYN);

    prep_kernel<<<BB * DD / 4 / 1024, 256>>>(x);
    triplet_mma<<<GRID, 256, SMEM_DYN>>>(t, o);
}